// round 1
// baseline (speedup 1.0000x reference)
#include <cuda_runtime.h>
#include <cuda_bf16.h>
#include <math.h>

#define NBOX 4096
#define CIN  64
#define CMID 128
#define FCD  256
#define POOL 7
#define NBIN 49          // POOL*POOL
#define FM_H 256
#define FM_W 256
#define FM_HW 65536
#define FCIN 6272        // CMID*49

// ---------------- scratch (no runtime allocation allowed) ----------------
__device__ float g_roi[(size_t)NBOX * CIN * NBIN];    //  51 MB
__device__ float g_c1 [(size_t)NBOX * CMID * NBIN];   // 103 MB
__device__ float g_c2 [(size_t)NBOX * CMID * NBIN];   // 103 MB
__device__ float g_fc1[(size_t)NBOX * FCD];           //   4 MB

// ---------------- ROI align ----------------
// one block per box, 256 threads. 14 sample positions per axis, bilinear taps
// precomputed in smem. Output g_roi[n][c][bin].
__global__ void roi_kernel(const float* __restrict__ feat,
                           const float* __restrict__ boxes)
{
    const int n = blockIdx.x;
    __shared__ float sbox[5];
    __shared__ int   sy0[14], sy1[14], sx0[14], sx1[14];
    __shared__ float sly[14], slx[14];
    __shared__ int   svy[14], svx[14];

    if (threadIdx.x < 5) sbox[threadIdx.x] = boxes[n * 5 + threadIdx.x];
    __syncthreads();

    const int   b  = (int)sbox[0];
    const float x1 = sbox[1], y1 = sbox[2], x2 = sbox[3], y2 = sbox[4];
    const float roi_w = fmaxf(x2 - x1, 1.0f);
    const float roi_h = fmaxf(y2 - y1, 1.0f);
    const float bin_w = roi_w / 7.0f;
    const float bin_h = roi_h / 7.0f;

    const int t = threadIdx.x;
    if (t < 28) {
        const int   i = t % 14;
        const float g = ((float)i + 0.5f) * 0.5f;   // (i+0.5)/sr, sr=2
        if (t < 14) {
            float c = y1 + bin_h * g;
            svy[i] = (c >= -1.0f && c <= 256.0f);
            float cc = fminf(fmaxf(c, 0.0f), 255.0f);
            int lo = (int)floorf(cc);
            sy0[i] = lo;
            sy1[i] = min(lo + 1, 255);
            sly[i] = cc - (float)lo;
        } else {
            float c = x1 + bin_w * g;
            svx[i] = (c >= -1.0f && c <= 256.0f);
            float cc = fminf(fmaxf(c, 0.0f), 255.0f);
            int lo = (int)floorf(cc);
            sx0[i] = lo;
            sx1[i] = min(lo + 1, 255);
            slx[i] = cc - (float)lo;
        }
    }
    __syncthreads();

    const float* fbase = feat + (size_t)b * CIN * FM_HW;
    float* outp = g_roi + (size_t)n * CIN * NBIN;

    for (int idx = t; idx < CIN * NBIN; idx += blockDim.x) {
        const int c   = idx / NBIN;
        const int bin = idx % NBIN;
        const int py  = bin / 7;
        const int px  = bin % 7;
        const float* fc = fbase + (size_t)c * FM_HW;
        float acc = 0.0f;
        #pragma unroll
        for (int sy = 0; sy < 2; sy++) {
            const int iy = py * 2 + sy;
            if (!svy[iy]) continue;
            const int   yy0 = sy0[iy], yy1 = sy1[iy];
            const float ly  = sly[iy], hy = 1.0f - ly;
            const float* r0 = fc + yy0 * FM_W;
            const float* r1 = fc + yy1 * FM_W;
            #pragma unroll
            for (int sx = 0; sx < 2; sx++) {
                const int ix = px * 2 + sx;
                if (!svx[ix]) continue;
                const int   xx0 = sx0[ix], xx1 = sx1[ix];
                const float lx  = slx[ix], hx = 1.0f - lx;
                acc += hy * (hx * __ldg(r0 + xx0) + lx * __ldg(r0 + xx1))
                     + ly * (hx * __ldg(r1 + xx0) + lx * __ldg(r1 + xx1));
            }
        }
        outp[idx] = acc * 0.25f;   // mean over 2x2 subsamples
    }
}

// ---------------- conv3x3 (SAME, pad 1) + bias + ReLU ----------------
// one block per box, 128 threads, thread = output channel.
// Input tile (CI x 9 x 9, zero padded) in static smem; all threads read the
// same smem word (broadcast, conflict-free). Weights register-cached per ci.
template <int CI>
__device__ __forceinline__ void conv_impl(const float* __restrict__ in,
                                          const float* __restrict__ w,
                                          const float* __restrict__ bias,
                                          float* __restrict__ out)
{
    __shared__ float xs[CI * 81];
    const int n  = blockIdx.x;
    const int co = threadIdx.x;

    const float* inp = in + (size_t)n * CI * NBIN;
    for (int i = threadIdx.x; i < CI * 81; i += blockDim.x) xs[i] = 0.0f;
    __syncthreads();
    for (int i = threadIdx.x; i < CI * NBIN; i += blockDim.x) {
        const int ci = i / NBIN, s = i % NBIN;
        const int y = s / 7, x = s % 7;
        xs[ci * 81 + (y + 1) * 9 + (x + 1)] = inp[i];
    }
    __syncthreads();

    float acc[NBIN];
    const float bv = bias[co];
    #pragma unroll
    for (int s = 0; s < NBIN; s++) acc[s] = bv;

    const float* wp = w + (size_t)co * CI * 9;
    for (int ci = 0; ci < CI; ci++) {
        float wv[9];
        #pragma unroll
        for (int k = 0; k < 9; k++) wv[k] = __ldg(wp + ci * 9 + k);
        const float* xc = xs + ci * 81;
        #pragma unroll
        for (int yy = 0; yy < 9; yy++) {
            float r[9];
            #pragma unroll
            for (int j = 0; j < 9; j++) r[j] = xc[yy * 9 + j];
            #pragma unroll
            for (int ky = 0; ky < 3; ky++) {
                const int y = yy - ky;          // compile-time resolved
                if (y < 0 || y > 6) continue;
                const float w0 = wv[ky * 3 + 0];
                const float w1 = wv[ky * 3 + 1];
                const float w2 = wv[ky * 3 + 2];
                #pragma unroll
                for (int x = 0; x < 7; x++) {
                    acc[y * 7 + x] += w0 * r[x] + w1 * r[x + 1] + w2 * r[x + 2];
                }
            }
        }
    }

    float* op = out + ((size_t)n * CMID + co) * NBIN;
    #pragma unroll
    for (int s = 0; s < NBIN; s++) op[s] = fmaxf(acc[s], 0.0f);
}

__global__ void conv1_kernel(const float* __restrict__ w, const float* __restrict__ b)
{
    conv_impl<CIN>(g_roi, w, b, g_c1);
}
__global__ void conv2_kernel(const float* __restrict__ w, const float* __restrict__ b)
{
    conv_impl<CMID>(g_c1, w, b, g_c2);
}

// ---------------- FC1: [4096,6272] x [6272,256] + bias + ReLU ----------------
__global__ void fc1_kernel(const float* __restrict__ Bw,
                           const float* __restrict__ bias)
{
    __shared__ float As[32][65];
    __shared__ float Bs[32][65];

    const int tm = threadIdx.x % 16;
    const int tn = threadIdx.x / 16;
    const int m0 = blockIdx.x * 64;
    const int n0 = blockIdx.y * 64;

    float acc[4][4] = {};

    for (int k0 = 0; k0 < FCIN; k0 += 32) {
        for (int i = threadIdx.x; i < 64 * 32; i += 256) {
            const int m = i / 32, k = i % 32;
            As[k][m] = g_c2[(size_t)(m0 + m) * FCIN + k0 + k];
        }
        for (int i = threadIdx.x; i < 32 * 64; i += 256) {
            const int k = i / 64, nn = i % 64;
            Bs[k][nn] = Bw[(size_t)(k0 + k) * FCD + n0 + nn];
        }
        __syncthreads();
        #pragma unroll
        for (int k = 0; k < 32; k++) {
            float a[4], bv[4];
            #pragma unroll
            for (int i = 0; i < 4; i++) a[i] = As[k][tm * 4 + i];
            #pragma unroll
            for (int j = 0; j < 4; j++) bv[j] = Bs[k][tn * 4 + j];
            #pragma unroll
            for (int i = 0; i < 4; i++)
                #pragma unroll
                for (int j = 0; j < 4; j++)
                    acc[i][j] += a[i] * bv[j];
        }
        __syncthreads();
    }

    #pragma unroll
    for (int i = 0; i < 4; i++) {
        const int m = m0 + tm * 4 + i;
        #pragma unroll
        for (int j = 0; j < 4; j++) {
            const int nn = n0 + tn * 4 + j;
            g_fc1[(size_t)m * FCD + nn] = fmaxf(acc[i][j] + bias[nn], 0.0f);
        }
    }
}

// ---------------- FC2: dot(256) + bias + sigmoid ----------------
__global__ void fc2_kernel(const float* __restrict__ w,
                           const float* __restrict__ b,
                           float* __restrict__ out)
{
    const int warp = (blockIdx.x * blockDim.x + threadIdx.x) >> 5;
    const int lane = threadIdx.x & 31;
    if (warp >= NBOX) return;
    const float* x = g_fc1 + (size_t)warp * FCD;
    float s = 0.0f;
    #pragma unroll
    for (int i = 0; i < 8; i++) s += x[lane + i * 32] * __ldg(w + lane + i * 32);
    #pragma unroll
    for (int o = 16; o; o >>= 1) s += __shfl_xor_sync(0xFFFFFFFFu, s, o);
    if (lane == 0) out[warp] = 1.0f / (1.0f + expf(-(s + b[0])));
}

// ---------------- launch ----------------
extern "C" void kernel_launch(void* const* d_in, const int* in_sizes, int n_in,
                              void* d_out, int out_size)
{
    const float* feat  = (const float*)d_in[0];
    const float* boxes = (const float*)d_in[1];
    const float* w1    = (const float*)d_in[2];
    const float* b1    = (const float*)d_in[3];
    const float* w2    = (const float*)d_in[4];
    const float* b2    = (const float*)d_in[5];
    const float* fw1   = (const float*)d_in[6];
    const float* fb1   = (const float*)d_in[7];
    const float* fw2   = (const float*)d_in[8];
    const float* fb2   = (const float*)d_in[9];
    float* out = (float*)d_out;

    roi_kernel  <<<NBOX, 256>>>(feat, boxes);
    conv1_kernel<<<NBOX, CMID>>>(w1, b1);
    conv2_kernel<<<NBOX, CMID>>>(w2, b2);
    dim3 g1(NBOX / 64, FCD / 64);
    fc1_kernel  <<<g1, 256>>>(fw1, fb1);
    fc2_kernel  <<<NBOX / 8, 256>>>(fw2, fb2, out);
}

// round 2
// speedup vs baseline: 3.4200x; 3.4200x over previous
#include <cuda_runtime.h>
#include <cuda_fp16.h>
#include <math.h>
#include <stdint.h>

#define NBOX 4096
#define CIN  64
#define CMID 128
#define FCD  256
#define NBIN 49
#define FM_H 256
#define FM_W 256
#define FM_HW 65536
#define FCIN 6272        // CMID*49

// ---------------- scratch ----------------
__device__ float g_a1 [(size_t)NBOX * 81 * CIN];     // padded NHWC roi out (85MB)
__device__ float g_a2 [(size_t)NBOX * 81 * CMID];    // padded NHWC conv1 out (170MB)
__device__ float g_c2m[(size_t)NBOX * FCIN];         // conv2 out, k-order bin*128+co (103MB)
__device__ float g_fc1[(size_t)NBOX * FCD];

__device__ __half g_wt1_hi[128 * 576];
__device__ __half g_wt1_lo[128 * 576];
__device__ __half g_wt2_hi[128 * 1152];
__device__ __half g_wt2_lo[128 * 1152];
__device__ __half g_fwt_hi[(size_t)256 * FCIN];
__device__ __half g_fwt_lo[(size_t)256 * FCIN];

// ---------------- helpers ----------------
__device__ __forceinline__ unsigned smem_u32(const void* p) {
    return (unsigned)__cvta_generic_to_shared(p);
}
__device__ __forceinline__ void split_f(float v, __half& h, __half& l) {
    h = __float2half_rn(v);
    l = __float2half_rn(v - __half2float(h));
}
__device__ __forceinline__ void ldsm4(unsigned addr, unsigned& r0, unsigned& r1,
                                      unsigned& r2, unsigned& r3) {
    asm volatile("ldmatrix.sync.aligned.m8n8.x4.shared.b16 {%0,%1,%2,%3}, [%4];"
                 : "=r"(r0), "=r"(r1), "=r"(r2), "=r"(r3) : "r"(addr));
}
__device__ __forceinline__ void mma16816(float* c, const unsigned* a, const unsigned* b) {
    asm volatile("mma.sync.aligned.m16n8k16.row.col.f32.f16.f16.f32 "
                 "{%0,%1,%2,%3}, {%4,%5,%6,%7}, {%8,%9}, {%0,%1,%2,%3};"
                 : "+f"(c[0]), "+f"(c[1]), "+f"(c[2]), "+f"(c[3])
                 : "r"(a[0]), "r"(a[1]), "r"(a[2]), "r"(a[3]), "r"(b[0]), "r"(b[1]));
}

// ---------------- weight prep (hi/lo fp16 planes, MMA-friendly K orders) ------
// wt[co][t*CI+ci] from w[co][ci][t] ; fwt[n][bin*128+co] from fw1[(co*49+bin)][n]
#define PREP_N1 (128 * 576)
#define PREP_N2 (128 * 1152)
#define PREP_N3 (256 * FCIN)
__global__ void prep_kernel(const float* __restrict__ w1,
                            const float* __restrict__ w2,
                            const float* __restrict__ fw1)
{
    int i = blockIdx.x * blockDim.x + threadIdx.x;
    if (i < PREP_N1) {
        int co = i / 576, k = i % 576;
        int t = k / 64, ci = k % 64;
        float v = w1[(co * 64 + ci) * 9 + t];
        split_f(v, g_wt1_hi[i], g_wt1_lo[i]);
    } else if (i < PREP_N1 + PREP_N2) {
        int j = i - PREP_N1;
        int co = j / 1152, k = j % 1152;
        int t = k / 128, ci = k % 128;
        float v = w2[(co * 128 + ci) * 9 + t];
        split_f(v, g_wt2_hi[j], g_wt2_lo[j]);
    } else if (i < PREP_N1 + PREP_N2 + PREP_N3) {
        int l = i - PREP_N1 - PREP_N2;
        int n = l / FCIN, kp = l % FCIN;
        int bin = kp / 128, co = kp % 128;
        float v = fw1[(size_t)(co * 49 + bin) * 256 + n];
        split_f(v, g_fwt_hi[l], g_fwt_lo[l]);
    }
}

// ---------------- ROI align -> padded NHWC fp32 ----------------
__global__ void roi_kernel(const float* __restrict__ feat,
                           const float* __restrict__ boxes)
{
    const int n = blockIdx.x;
    __shared__ float sbox[5];
    __shared__ int   sy0[14], sy1[14], sx0[14], sx1[14];
    __shared__ float sly[14], slx[14];
    __shared__ int   svy[14], svx[14];
    __shared__ float stage[49 * 65];

    if (threadIdx.x < 5) sbox[threadIdx.x] = boxes[n * 5 + threadIdx.x];
    __syncthreads();

    const int   b  = (int)sbox[0];
    const float x1 = sbox[1], y1 = sbox[2], x2 = sbox[3], y2 = sbox[4];
    const float bin_w = fmaxf(x2 - x1, 1.0f) / 7.0f;
    const float bin_h = fmaxf(y2 - y1, 1.0f) / 7.0f;

    const int t = threadIdx.x;
    if (t < 28) {
        const int   i = t % 14;
        const float g = ((float)i + 0.5f) * 0.5f;
        if (t < 14) {
            float c = y1 + bin_h * g;
            svy[i] = (c >= -1.0f && c <= 256.0f);
            float cc = fminf(fmaxf(c, 0.0f), 255.0f);
            int lo = (int)floorf(cc);
            sy0[i] = lo; sy1[i] = min(lo + 1, 255); sly[i] = cc - (float)lo;
        } else {
            float c = x1 + bin_w * g;
            svx[i] = (c >= -1.0f && c <= 256.0f);
            float cc = fminf(fmaxf(c, 0.0f), 255.0f);
            int lo = (int)floorf(cc);
            sx0[i] = lo; sx1[i] = min(lo + 1, 255); slx[i] = cc - (float)lo;
        }
    }
    __syncthreads();

    const float* fbase = feat + (size_t)b * CIN * FM_HW;
    for (int idx = t; idx < CIN * NBIN; idx += blockDim.x) {
        const int c   = idx / NBIN;
        const int bin = idx % NBIN;
        const int py  = bin / 7, px = bin % 7;
        const float* fc = fbase + (size_t)c * FM_HW;
        float acc = 0.0f;
        #pragma unroll
        for (int sy = 0; sy < 2; sy++) {
            const int iy = py * 2 + sy;
            if (!svy[iy]) continue;
            const int   yy0 = sy0[iy], yy1 = sy1[iy];
            const float ly  = sly[iy], hy = 1.0f - ly;
            const float* r0 = fc + yy0 * FM_W;
            const float* r1 = fc + yy1 * FM_W;
            #pragma unroll
            for (int sx = 0; sx < 2; sx++) {
                const int ix = px * 2 + sx;
                if (!svx[ix]) continue;
                const int   xx0 = sx0[ix], xx1 = sx1[ix];
                const float lx  = slx[ix], hx = 1.0f - lx;
                acc += hy * (hx * __ldg(r0 + xx0) + lx * __ldg(r0 + xx1))
                     + ly * (hx * __ldg(r1 + xx0) + lx * __ldg(r1 + xx1));
            }
        }
        stage[bin * 65 + c] = acc * 0.25f;
    }
    __syncthreads();

    float* outp = g_a1 + (size_t)n * 81 * CIN;
    for (int idx = t; idx < 81 * CIN; idx += blockDim.x) {
        const int sp = idx >> 6, ci = idx & 63;
        const int y = sp / 9, x = sp % 9;
        float v = 0.0f;
        if (y >= 1 && y <= 7 && x >= 1 && x <= 7)
            v = stage[((y - 1) * 7 + (x - 1)) * 65 + ci];
        outp[idx] = v;
    }
}

// ---------------- conv3x3 as implicit MMA GEMM ----------------
// Block: 2 boxes (M=128 rows, 98 real), N=128 cout. K' = CI*9 with (tap,ci) order,
// fp16x2 split -> 3 mma per k16 block. A resident in smem (padded NHWC hi/lo),
// B (weights) reg-double-buffered per k-block.
template <int CI, bool OUT_PAD>
__global__ __launch_bounds__(256, 2) void conv_mma(const float* __restrict__ bias)
{
    constexpr int ROWH  = CI + 8;          // smem row in halves (bank-conflict pad)
    constexpr int K     = CI * 9;
    constexpr int NKB   = K / 16;
    constexpr int KC16  = CI / 16;
    constexpr int APLN  = 2 * 81 * ROWH;   // halves per plane

    const float*  gin   = (CI == 64) ? g_a1 : g_a2;
    const __half* wt_hi = (CI == 64) ? g_wt1_hi : g_wt2_hi;
    const __half* wt_lo = (CI == 64) ? g_wt1_lo : g_wt2_lo;
    float*        gout  = OUT_PAD ? g_a2 : g_c2m;

    extern __shared__ __half sm[];
    __half* sAh = sm;
    __half* sAl = sm + APLN;
    __half* sBh = sm + 2 * APLN;
    __half* sBl = sBh + 128 * 24;

    const int n0   = blockIdx.x * 2;
    const int t    = threadIdx.x;
    const int w    = t >> 5, lane = t & 31;
    const int wm   = w >> 1, wn = w & 1;

    // ---- fill A (fp32 -> hi/lo fp16) ----
    const float* in0 = gin + (size_t)n0 * 81 * CI;
    for (int i = t; i < 2 * 81 * CI; i += 256) {
        const int sp = i / CI, ci = i % CI;
        __half h, l; split_f(in0[i], h, l);
        sAh[sp * ROWH + ci] = h;
        sAl[sp * ROWH + ci] = l;
    }

    // ---- zero output borders (padded NHWC consumer) ----
    if (OUT_PAD) {
        for (int i = t; i < 2 * 81 * 128; i += 256) {
            const int bx = i / (81 * 128), r = i % (81 * 128);
            const int sp = r >> 7;
            const int y = sp / 9, x = sp % 9;
            if (y == 0 || y == 8 || x == 0 || x == 8)
                gout[(size_t)(n0 + bx) * 81 * 128 + r] = 0.0f;
        }
    }

    // ---- B prefetch regs ----
    const int bco = t >> 1, bkh = (t & 1) * 8;
    uint4 pfh, pfl;
    {
        const size_t off = (size_t)bco * K + bkh;   // kb=0: tap 0, kc 0
        pfh = *(const uint4*)(wt_hi + off);
        pfl = *(const uint4*)(wt_lo + off);
    }

    // ---- per-lane ldmatrix bases ----
    unsigned rowbase[2];
    {
        const int khoff = (lane >> 4) * 16;
        #pragma unroll
        for (int mt = 0; mt < 2; mt++) {
            const int m = wm * 32 + mt * 16 + (lane & 15);
            int box = 0, bs = 0;
            if (m < 98) { box = m / 49; const int bin = m % 49; bs = (bin / 7) * 9 + (bin % 7); }
            rowbase[mt] = (unsigned)((box * 81 + bs) * ROWH * 2 + khoff);
        }
    }
    const unsigned sAh_u = smem_u32(sAh), sAl_u = smem_u32(sAl);
    const unsigned sBh_u = smem_u32(sBh), sBl_u = smem_u32(sBl);
    const int nl = (lane & 7) | ((lane >> 4) << 3);
    const unsigned bbase = (unsigned)((wn * 64 + nl) * 48 + (lane & 8) * 2);

    float acc[2][8][4];
    #pragma unroll
    for (int i = 0; i < 2; i++)
        #pragma unroll
        for (int j = 0; j < 8; j++)
            #pragma unroll
            for (int q = 0; q < 4; q++) acc[i][j][q] = 0.0f;

    // ---- main K loop ----
    for (int kb = 0; kb < NKB; kb++) {
        __syncthreads();
        *(uint4*)(sBh + bco * 24 + bkh) = pfh;
        *(uint4*)(sBl + bco * 24 + bkh) = pfl;
        __syncthreads();
        if (kb + 1 < NKB) {
            const int tp = (kb + 1) / KC16, kc = ((kb + 1) % KC16) * 16;
            const size_t off = (size_t)bco * K + tp * CI + kc + bkh;
            pfh = *(const uint4*)(wt_hi + off);
            pfl = *(const uint4*)(wt_lo + off);
        }

        const int tp = kb / KC16, kc = (kb % KC16) * 16;
        const int dt = (tp / 3) * 9 + (tp % 3);
        const unsigned aoff = (unsigned)(dt * ROWH * 2 + kc * 2);

        unsigned ah[2][4], al[2][4];
        #pragma unroll
        for (int mt = 0; mt < 2; mt++) {
            ldsm4(sAh_u + rowbase[mt] + aoff, ah[mt][0], ah[mt][1], ah[mt][2], ah[mt][3]);
            ldsm4(sAl_u + rowbase[mt] + aoff, al[mt][0], al[mt][1], al[mt][2], al[mt][3]);
        }
        #pragma unroll
        for (int np = 0; np < 4; np++) {
            unsigned bh[4], bl[4];
            ldsm4(sBh_u + bbase + np * 16 * 48, bh[0], bh[1], bh[2], bh[3]);
            ldsm4(sBl_u + bbase + np * 16 * 48, bl[0], bl[1], bl[2], bl[3]);
            #pragma unroll
            for (int mt = 0; mt < 2; mt++) {
                mma16816(acc[mt][np * 2 + 0], ah[mt], bh + 0);
                mma16816(acc[mt][np * 2 + 0], ah[mt], bl + 0);
                mma16816(acc[mt][np * 2 + 0], al[mt], bh + 0);
                mma16816(acc[mt][np * 2 + 1], ah[mt], bh + 2);
                mma16816(acc[mt][np * 2 + 1], ah[mt], bl + 2);
                mma16816(acc[mt][np * 2 + 1], al[mt], bh + 2);
            }
        }
    }

    // ---- epilogue: bias + ReLU -> gmem ----
    #pragma unroll
    for (int mt = 0; mt < 2; mt++) {
        const int mrow0 = wm * 32 + mt * 16 + (lane >> 2);
        #pragma unroll
        for (int hf = 0; hf < 2; hf++) {
            const int m = mrow0 + hf * 8;
            if (m >= 98) continue;
            const int box = n0 + m / 49, bin = m % 49;
            #pragma unroll
            for (int nt = 0; nt < 8; nt++) {
                const int co = wn * 64 + nt * 8 + (lane & 3) * 2;
                float2 v;
                v.x = fmaxf(acc[mt][nt][hf * 2 + 0] + __ldg(bias + co), 0.0f);
                v.y = fmaxf(acc[mt][nt][hf * 2 + 1] + __ldg(bias + co + 1), 0.0f);
                size_t o;
                if (OUT_PAD) {
                    const int y = bin / 7, x = bin % 7;
                    o = ((size_t)box * 81 + (y + 1) * 9 + (x + 1)) * 128 + co;
                } else {
                    o = (size_t)box * FCIN + bin * 128 + co;
                }
                *(float2*)(gout + o) = v;
            }
        }
    }
}

// ---------------- FC1 GEMM: [4096,6272] x [6272,256] ----------------
__global__ __launch_bounds__(128) void fc1_mma(const float* __restrict__ bias)
{
    __shared__ __half sAh[64 * 24], sAl[64 * 24], sBh[64 * 24], sBl[64 * 24];
    const int t = threadIdx.x, w = t >> 5, lane = t & 31;
    const int wm = w & 1, wn = w >> 1;
    const int m0 = blockIdx.x * 64, nb0 = blockIdx.y * 64;
    const int r = t >> 1, kh = (t & 1) * 8;

    float4 pa0, pa1; uint4 pbh, pbl;
    {
        const float* ap = g_c2m + (size_t)(m0 + r) * FCIN + kh;
        pa0 = *(const float4*)ap; pa1 = *(const float4*)(ap + 4);
        const size_t bo = (size_t)(nb0 + r) * FCIN + kh;
        pbh = *(const uint4*)(g_fwt_hi + bo);
        pbl = *(const uint4*)(g_fwt_lo + bo);
    }

    unsigned arow[2];
    {
        const int khoff = (lane >> 4) * 16;
        #pragma unroll
        for (int mt = 0; mt < 2; mt++)
            arow[mt] = (unsigned)((wm * 32 + mt * 16 + (lane & 15)) * 48 + khoff);
    }
    const int nl = (lane & 7) | ((lane >> 4) << 3);
    const unsigned bbase = (unsigned)((wn * 32 + nl) * 48 + (lane & 8) * 2);
    const unsigned sAh_u = smem_u32(sAh), sAl_u = smem_u32(sAl);
    const unsigned sBh_u = smem_u32(sBh), sBl_u = smem_u32(sBl);

    float acc[2][4][4];
    #pragma unroll
    for (int i = 0; i < 2; i++)
        #pragma unroll
        for (int j = 0; j < 4; j++)
            #pragma unroll
            for (int q = 0; q < 4; q++) acc[i][j][q] = 0.0f;

    const int NKB = FCIN / 16;   // 392
    for (int kb = 0; kb < NKB; kb++) {
        __syncthreads();
        {
            float av[8] = {pa0.x, pa0.y, pa0.z, pa0.w, pa1.x, pa1.y, pa1.z, pa1.w};
            __half h[8], l[8];
            #pragma unroll
            for (int j = 0; j < 8; j++) split_f(av[j], h[j], l[j]);
            *(uint4*)(sAh + r * 24 + kh) = *(uint4*)h;
            *(uint4*)(sAl + r * 24 + kh) = *(uint4*)l;
            *(uint4*)(sBh + r * 24 + kh) = pbh;
            *(uint4*)(sBl + r * 24 + kh) = pbl;
        }
        __syncthreads();
        if (kb + 1 < NKB) {
            const float* ap = g_c2m + (size_t)(m0 + r) * FCIN + (kb + 1) * 16 + kh;
            pa0 = *(const float4*)ap; pa1 = *(const float4*)(ap + 4);
            const size_t bo = (size_t)(nb0 + r) * FCIN + (kb + 1) * 16 + kh;
            pbh = *(const uint4*)(g_fwt_hi + bo);
            pbl = *(const uint4*)(g_fwt_lo + bo);
        }

        unsigned ah[2][4], al[2][4];
        #pragma unroll
        for (int mt = 0; mt < 2; mt++) {
            ldsm4(sAh_u + arow[mt], ah[mt][0], ah[mt][1], ah[mt][2], ah[mt][3]);
            ldsm4(sAl_u + arow[mt], al[mt][0], al[mt][1], al[mt][2], al[mt][3]);
        }
        #pragma unroll
        for (int np = 0; np < 2; np++) {
            unsigned bh[4], bl[4];
            ldsm4(sBh_u + bbase + np * 16 * 48, bh[0], bh[1], bh[2], bh[3]);
            ldsm4(sBl_u + bbase + np * 16 * 48, bl[0], bl[1], bl[2], bl[3]);
            #pragma unroll
            for (int mt = 0; mt < 2; mt++) {
                mma16816(acc[mt][np * 2 + 0], ah[mt], bh + 0);
                mma16816(acc[mt][np * 2 + 0], ah[mt], bl + 0);
                mma16816(acc[mt][np * 2 + 0], al[mt], bh + 0);
                mma16816(acc[mt][np * 2 + 1], ah[mt], bh + 2);
                mma16816(acc[mt][np * 2 + 1], ah[mt], bl + 2);
                mma16816(acc[mt][np * 2 + 1], al[mt], bh + 2);
            }
        }
    }

    #pragma unroll
    for (int mt = 0; mt < 2; mt++) {
        const int mrow0 = m0 + wm * 32 + mt * 16 + (lane >> 2);
        #pragma unroll
        for (int hf = 0; hf < 2; hf++) {
            const int m = mrow0 + hf * 8;
            #pragma unroll
            for (int nt = 0; nt < 4; nt++) {
                const int col = nb0 + wn * 32 + nt * 8 + (lane & 3) * 2;
                float2 v;
                v.x = fmaxf(acc[mt][nt][hf * 2 + 0] + __ldg(bias + col), 0.0f);
                v.y = fmaxf(acc[mt][nt][hf * 2 + 1] + __ldg(bias + col + 1), 0.0f);
                *(float2*)(g_fc1 + (size_t)m * FCD + col) = v;
            }
        }
    }
}

// ---------------- FC2 ----------------
__global__ void fc2_kernel(const float* __restrict__ w,
                           const float* __restrict__ b,
                           float* __restrict__ out)
{
    const int warp = (blockIdx.x * blockDim.x + threadIdx.x) >> 5;
    const int lane = threadIdx.x & 31;
    if (warp >= NBOX) return;
    const float* x = g_fc1 + (size_t)warp * FCD;
    float s = 0.0f;
    #pragma unroll
    for (int i = 0; i < 8; i++) s += x[lane + i * 32] * __ldg(w + lane + i * 32);
    #pragma unroll
    for (int o = 16; o; o >>= 1) s += __shfl_xor_sync(0xFFFFFFFFu, s, o);
    if (lane == 0) out[warp] = 1.0f / (1.0f + expf(-(s + b[0])));
}

// ---------------- launch ----------------
extern "C" void kernel_launch(void* const* d_in, const int* in_sizes, int n_in,
                              void* d_out, int out_size)
{
    const float* feat  = (const float*)d_in[0];
    const float* boxes = (const float*)d_in[1];
    const float* w1    = (const float*)d_in[2];
    const float* b1    = (const float*)d_in[3];
    const float* w2    = (const float*)d_in[4];
    const float* b2    = (const float*)d_in[5];
    const float* fw1   = (const float*)d_in[6];
    const float* fb1   = (const float*)d_in[7];
    const float* fw2   = (const float*)d_in[8];
    const float* fb2   = (const float*)d_in[9];
    float* out = (float*)d_out;

    // dynamic smem sizes
    const int SMEM1 = (2 * (2 * 81 * (64 + 8)) + 2 * 128 * 24) * 2;    // 58944
    const int SMEM2 = (2 * (2 * 81 * (128 + 8)) + 2 * 128 * 24) * 2;   // 100416
    cudaFuncSetAttribute(conv_mma<64, true>,   cudaFuncAttributeMaxDynamicSharedMemorySize, SMEM1);
    cudaFuncSetAttribute(conv_mma<128, false>, cudaFuncAttributeMaxDynamicSharedMemorySize, SMEM2);

    const int PREP_TOTAL = PREP_N1 + PREP_N2 + PREP_N3;
    prep_kernel<<<(PREP_TOTAL + 255) / 256, 256>>>(w1, w2, fw1);
    roi_kernel<<<NBOX, 256>>>(feat, boxes);
    conv_mma<64, true>  <<<NBOX / 2, 256, SMEM1>>>(b1);
    conv_mma<128, false><<<NBOX / 2, 256, SMEM2>>>(b2);
    dim3 gfc(NBOX / 64, FCD / 64);
    fc1_mma<<<gfc, 128>>>(fb1);
    fc2_kernel<<<NBOX / 8, 256>>>(fw2, fb2, out);
}

// round 3
// speedup vs baseline: 3.4238x; 1.0011x over previous
#include <cuda_runtime.h>
#include <cuda_fp16.h>
#include <math.h>
#include <stdint.h>

#define NBOX 4096
#define CIN  64
#define CMID 128
#define FCD  256
#define NBIN 49
#define FM_H 256
#define FM_W 256
#define FM_HW 65536
#define FCIN 6272        // CMID*49

// ---------------- scratch ----------------
__device__ float g_a1 [(size_t)NBOX * 81 * CIN];     // padded NHWC roi out (85MB)
__device__ float g_a2 [(size_t)NBOX * 81 * CMID];    // padded NHWC conv1 out (170MB)
__device__ float g_c2m[(size_t)NBOX * FCIN];         // conv2 out, k-order bin*128+co (103MB)
__device__ float g_fc1[(size_t)NBOX * FCD];

__device__ __half g_wt1_hi[128 * 576];
__device__ __half g_wt1_lo[128 * 576];
__device__ __half g_wt2_hi[128 * 1152];
__device__ __half g_wt2_lo[128 * 1152];
__device__ __half g_fwt_hi[(size_t)256 * FCIN];
__device__ __half g_fwt_lo[(size_t)256 * FCIN];

// ---------------- helpers ----------------
__device__ __forceinline__ unsigned smem_u32(const void* p) {
    return (unsigned)__cvta_generic_to_shared(p);
}
__device__ __forceinline__ void split_f(float v, __half& h, __half& l) {
    h = __float2half_rn(v);
    l = __float2half_rn(v - __half2float(h));
}
__device__ __forceinline__ void ldsm4(unsigned addr, unsigned& r0, unsigned& r1,
                                      unsigned& r2, unsigned& r3) {
    asm volatile("ldmatrix.sync.aligned.m8n8.x4.shared.b16 {%0,%1,%2,%3}, [%4];"
                 : "=r"(r0), "=r"(r1), "=r"(r2), "=r"(r3) : "r"(addr));
}
__device__ __forceinline__ void mma16816(float* c, const unsigned* a, const unsigned* b) {
    asm volatile("mma.sync.aligned.m16n8k16.row.col.f32.f16.f16.f32 "
                 "{%0,%1,%2,%3}, {%4,%5,%6,%7}, {%8,%9}, {%0,%1,%2,%3};"
                 : "+f"(c[0]), "+f"(c[1]), "+f"(c[2]), "+f"(c[3])
                 : "r"(a[0]), "r"(a[1]), "r"(a[2]), "r"(a[3]), "r"(b[0]), "r"(b[1]));
}

// ---------------- weight prep (hi/lo fp16 planes, MMA-friendly K orders) ------
// wt[co][t*CI+ci] from w[co][ci][t] ; fwt[n][bin*128+co] from fw1[(co*49+bin)][n]
#define PREP_N1 (128 * 576)
#define PREP_N2 (128 * 1152)
#define PREP_N3 (256 * FCIN)
__global__ void prep_kernel(const float* __restrict__ w1,
                            const float* __restrict__ w2,
                            const float* __restrict__ fw1)
{
    int i = blockIdx.x * blockDim.x + threadIdx.x;
    if (i < PREP_N1) {
        int co = i / 576, k = i % 576;
        int t = k / 64, ci = k % 64;
        float v = w1[(co * 64 + ci) * 9 + t];
        split_f(v, g_wt1_hi[i], g_wt1_lo[i]);
    } else if (i < PREP_N1 + PREP_N2) {
        int j = i - PREP_N1;
        int co = j / 1152, k = j % 1152;
        int t = k / 128, ci = k % 128;
        float v = w2[(co * 128 + ci) * 9 + t];
        split_f(v, g_wt2_hi[j], g_wt2_lo[j]);
    } else if (i < PREP_N1 + PREP_N2 + PREP_N3) {
        int l = i - PREP_N1 - PREP_N2;
        int n = l / FCIN, kp = l % FCIN;
        int bin = kp / 128, co = kp % 128;
        float v = fw1[(size_t)(co * 49 + bin) * 256 + n];
        split_f(v, g_fwt_hi[l], g_fwt_lo[l]);
    }
}

// ---------------- ROI align -> padded NHWC fp32 ----------------
__global__ void roi_kernel(const float* __restrict__ feat,
                           const float* __restrict__ boxes)
{
    const int n = blockIdx.x;
    __shared__ float sbox[5];
    __shared__ int   sy0[14], sy1[14], sx0[14], sx1[14];
    __shared__ float sly[14], slx[14];
    __shared__ int   svy[14], svx[14];
    __shared__ float stage[49 * 65];

    if (threadIdx.x < 5) sbox[threadIdx.x] = boxes[n * 5 + threadIdx.x];
    __syncthreads();

    const int   b  = (int)sbox[0];
    const float x1 = sbox[1], y1 = sbox[2], x2 = sbox[3], y2 = sbox[4];
    const float bin_w = fmaxf(x2 - x1, 1.0f) / 7.0f;
    const float bin_h = fmaxf(y2 - y1, 1.0f) / 7.0f;

    const int t = threadIdx.x;
    if (t < 28) {
        const int   i = t % 14;
        const float g = ((float)i + 0.5f) * 0.5f;
        if (t < 14) {
            float c = y1 + bin_h * g;
            svy[i] = (c >= -1.0f && c <= 256.0f);
            float cc = fminf(fmaxf(c, 0.0f), 255.0f);
            int lo = (int)floorf(cc);
            sy0[i] = lo; sy1[i] = min(lo + 1, 255); sly[i] = cc - (float)lo;
        } else {
            float c = x1 + bin_w * g;
            svx[i] = (c >= -1.0f && c <= 256.0f);
            float cc = fminf(fmaxf(c, 0.0f), 255.0f);
            int lo = (int)floorf(cc);
            sx0[i] = lo; sx1[i] = min(lo + 1, 255); slx[i] = cc - (float)lo;
        }
    }
    __syncthreads();

    const float* fbase = feat + (size_t)b * CIN * FM_HW;
    for (int idx = t; idx < CIN * NBIN; idx += blockDim.x) {
        const int c   = idx / NBIN;
        const int bin = idx % NBIN;
        const int py  = bin / 7, px = bin % 7;
        const float* fc = fbase + (size_t)c * FM_HW;
        float acc = 0.0f;
        #pragma unroll
        for (int sy = 0; sy < 2; sy++) {
            const int iy = py * 2 + sy;
            if (!svy[iy]) continue;
            const int   yy0 = sy0[iy], yy1 = sy1[iy];
            const float ly  = sly[iy], hy = 1.0f - ly;
            const float* r0 = fc + yy0 * FM_W;
            const float* r1 = fc + yy1 * FM_W;
            #pragma unroll
            for (int sx = 0; sx < 2; sx++) {
                const int ix = px * 2 + sx;
                if (!svx[ix]) continue;
                const int   xx0 = sx0[ix], xx1 = sx1[ix];
                const float lx  = slx[ix], hx = 1.0f - lx;
                acc += hy * (hx * __ldg(r0 + xx0) + lx * __ldg(r0 + xx1))
                     + ly * (hx * __ldg(r1 + xx0) + lx * __ldg(r1 + xx1));
            }
        }
        stage[bin * 65 + c] = acc * 0.25f;
    }
    __syncthreads();

    float* outp = g_a1 + (size_t)n * 81 * CIN;
    for (int idx = t; idx < 81 * CIN; idx += blockDim.x) {
        const int sp = idx >> 6, ci = idx & 63;
        const int y = sp / 9, x = sp % 9;
        float v = 0.0f;
        if (y >= 1 && y <= 7 && x >= 1 && x <= 7)
            v = stage[((y - 1) * 7 + (x - 1)) * 65 + ci];
        outp[idx] = v;
    }
}

// ---------------- conv3x3 as implicit MMA GEMM ----------------
// Block: 2 boxes (M=128 rows, 98 real), N=128 cout. K' = CI*9 with (tap,ci) order,
// fp16x2 split -> 3 mma per k16 block. A resident in smem (padded NHWC hi/lo),
// B (weights) reg-double-buffered per k-block.
template <int CI, bool OUT_PAD>
__global__ __launch_bounds__(256, 2) void conv_mma(const float* __restrict__ bias)
{
    constexpr int ROWH  = CI + 8;          // smem row in halves (bank-conflict pad)
    constexpr int K     = CI * 9;
    constexpr int NKB   = K / 16;
    constexpr int KC16  = CI / 16;
    constexpr int APLN  = 2 * 81 * ROWH;   // halves per plane

    const float*  gin   = (CI == 64) ? g_a1 : g_a2;
    const __half* wt_hi = (CI == 64) ? g_wt1_hi : g_wt2_hi;
    const __half* wt_lo = (CI == 64) ? g_wt1_lo : g_wt2_lo;
    float*        gout  = OUT_PAD ? g_a2 : g_c2m;

    extern __shared__ __half sm[];
    __half* sAh = sm;
    __half* sAl = sm + APLN;
    __half* sBh = sm + 2 * APLN;
    __half* sBl = sBh + 128 * 24;

    const int n0   = blockIdx.x * 2;
    const int t    = threadIdx.x;
    const int w    = t >> 5, lane = t & 31;
    const int wm   = w >> 1, wn = w & 1;

    // ---- fill A (fp32 -> hi/lo fp16) ----
    const float* in0 = gin + (size_t)n0 * 81 * CI;
    for (int i = t; i < 2 * 81 * CI; i += 256) {
        const int sp = i / CI, ci = i % CI;
        __half h, l; split_f(in0[i], h, l);
        sAh[sp * ROWH + ci] = h;
        sAl[sp * ROWH + ci] = l;
    }

    // ---- zero output borders (padded NHWC consumer) ----
    if (OUT_PAD) {
        for (int i = t; i < 2 * 81 * 128; i += 256) {
            const int bx = i / (81 * 128), r = i % (81 * 128);
            const int sp = r >> 7;
            const int y = sp / 9, x = sp % 9;
            if (y == 0 || y == 8 || x == 0 || x == 8)
                gout[(size_t)(n0 + bx) * 81 * 128 + r] = 0.0f;
        }
    }

    // ---- B prefetch regs ----
    const int bco = t >> 1, bkh = (t & 1) * 8;
    uint4 pfh, pfl;
    {
        const size_t off = (size_t)bco * K + bkh;   // kb=0: tap 0, kc 0
        pfh = *(const uint4*)(wt_hi + off);
        pfl = *(const uint4*)(wt_lo + off);
    }

    // ---- per-lane ldmatrix bases ----
    unsigned rowbase[2];
    {
        const int khoff = (lane >> 4) * 16;
        #pragma unroll
        for (int mt = 0; mt < 2; mt++) {
            const int m = wm * 32 + mt * 16 + (lane & 15);
            int box = 0, bs = 0;
            if (m < 98) { box = m / 49; const int bin = m % 49; bs = (bin / 7) * 9 + (bin % 7); }
            rowbase[mt] = (unsigned)((box * 81 + bs) * ROWH * 2 + khoff);
        }
    }
    const unsigned sAh_u = smem_u32(sAh), sAl_u = smem_u32(sAl);
    const unsigned sBh_u = smem_u32(sBh), sBl_u = smem_u32(sBl);
    const int nl = (lane & 7) | ((lane >> 4) << 3);
    const unsigned bbase = (unsigned)((wn * 64 + nl) * 48 + (lane & 8) * 2);

    float acc[2][8][4];
    #pragma unroll
    for (int i = 0; i < 2; i++)
        #pragma unroll
        for (int j = 0; j < 8; j++)
            #pragma unroll
            for (int q = 0; q < 4; q++) acc[i][j][q] = 0.0f;

    // ---- main K loop ----
    for (int kb = 0; kb < NKB; kb++) {
        __syncthreads();
        *(uint4*)(sBh + bco * 24 + bkh) = pfh;
        *(uint4*)(sBl + bco * 24 + bkh) = pfl;
        __syncthreads();
        if (kb + 1 < NKB) {
            const int tp = (kb + 1) / KC16, kc = ((kb + 1) % KC16) * 16;
            const size_t off = (size_t)bco * K + tp * CI + kc + bkh;
            pfh = *(const uint4*)(wt_hi + off);
            pfl = *(const uint4*)(wt_lo + off);
        }

        const int tp = kb / KC16, kc = (kb % KC16) * 16;
        const int dt = (tp / 3) * 9 + (tp % 3);
        const unsigned aoff = (unsigned)(dt * ROWH * 2 + kc * 2);

        unsigned ah[2][4], al[2][4];
        #pragma unroll
        for (int mt = 0; mt < 2; mt++) {
            ldsm4(sAh_u + rowbase[mt] + aoff, ah[mt][0], ah[mt][1], ah[mt][2], ah[mt][3]);
            ldsm4(sAl_u + rowbase[mt] + aoff, al[mt][0], al[mt][1], al[mt][2], al[mt][3]);
        }
        #pragma unroll
        for (int np = 0; np < 4; np++) {
            unsigned bh[4], bl[4];
            ldsm4(sBh_u + bbase + np * 16 * 48, bh[0], bh[1], bh[2], bh[3]);
            ldsm4(sBl_u + bbase + np * 16 * 48, bl[0], bl[1], bl[2], bl[3]);
            #pragma unroll
            for (int mt = 0; mt < 2; mt++) {
                mma16816(acc[mt][np * 2 + 0], ah[mt], bh + 0);
                mma16816(acc[mt][np * 2 + 0], ah[mt], bl + 0);
                mma16816(acc[mt][np * 2 + 0], al[mt], bh + 0);
                mma16816(acc[mt][np * 2 + 1], ah[mt], bh + 2);
                mma16816(acc[mt][np * 2 + 1], ah[mt], bl + 2);
                mma16816(acc[mt][np * 2 + 1], al[mt], bh + 2);
            }
        }
    }

    // ---- epilogue: bias + ReLU -> gmem ----
    #pragma unroll
    for (int mt = 0; mt < 2; mt++) {
        const int mrow0 = wm * 32 + mt * 16 + (lane >> 2);
        #pragma unroll
        for (int hf = 0; hf < 2; hf++) {
            const int m = mrow0 + hf * 8;
            if (m >= 98) continue;
            const int box = n0 + m / 49, bin = m % 49;
            #pragma unroll
            for (int nt = 0; nt < 8; nt++) {
                const int co = wn * 64 + nt * 8 + (lane & 3) * 2;
                float2 v;
                v.x = fmaxf(acc[mt][nt][hf * 2 + 0] + __ldg(bias + co), 0.0f);
                v.y = fmaxf(acc[mt][nt][hf * 2 + 1] + __ldg(bias + co + 1), 0.0f);
                size_t o;
                if (OUT_PAD) {
                    const int y = bin / 7, x = bin % 7;
                    o = ((size_t)box * 81 + (y + 1) * 9 + (x + 1)) * 128 + co;
                } else {
                    o = (size_t)box * FCIN + bin * 128 + co;
                }
                *(float2*)(gout + o) = v;
            }
        }
    }
}

// ---------------- FC1 GEMM: [4096,6272] x [6272,256] ----------------
__global__ __launch_bounds__(128) void fc1_mma(const float* __restrict__ bias)
{
    __shared__ __half sAh[64 * 24], sAl[64 * 24], sBh[64 * 24], sBl[64 * 24];
    const int t = threadIdx.x, w = t >> 5, lane = t & 31;
    const int wm = w & 1, wn = w >> 1;
    const int m0 = blockIdx.x * 64, nb0 = blockIdx.y * 64;
    const int r = t >> 1, kh = (t & 1) * 8;

    float4 pa0, pa1; uint4 pbh, pbl;
    {
        const float* ap = g_c2m + (size_t)(m0 + r) * FCIN + kh;
        pa0 = *(const float4*)ap; pa1 = *(const float4*)(ap + 4);
        const size_t bo = (size_t)(nb0 + r) * FCIN + kh;
        pbh = *(const uint4*)(g_fwt_hi + bo);
        pbl = *(const uint4*)(g_fwt_lo + bo);
    }

    unsigned arow[2];
    {
        const int khoff = (lane >> 4) * 16;
        #pragma unroll
        for (int mt = 0; mt < 2; mt++)
            arow[mt] = (unsigned)((wm * 32 + mt * 16 + (lane & 15)) * 48 + khoff);
    }
    const int nl = (lane & 7) | ((lane >> 4) << 3);
    const unsigned bbase = (unsigned)((wn * 32 + nl) * 48 + (lane & 8) * 2);
    const unsigned sAh_u = smem_u32(sAh), sAl_u = smem_u32(sAl);
    const unsigned sBh_u = smem_u32(sBh), sBl_u = smem_u32(sBl);

    float acc[2][4][4];
    #pragma unroll
    for (int i = 0; i < 2; i++)
        #pragma unroll
        for (int j = 0; j < 4; j++)
            #pragma unroll
            for (int q = 0; q < 4; q++) acc[i][j][q] = 0.0f;

    const int NKB = FCIN / 16;   // 392
    for (int kb = 0; kb < NKB; kb++) {
        __syncthreads();
        {
            float av[8] = {pa0.x, pa0.y, pa0.z, pa0.w, pa1.x, pa1.y, pa1.z, pa1.w};
            __half h[8], l[8];
            #pragma unroll
            for (int j = 0; j < 8; j++) split_f(av[j], h[j], l[j]);
            *(uint4*)(sAh + r * 24 + kh) = *(uint4*)h;
            *(uint4*)(sAl + r * 24 + kh) = *(uint4*)l;
            *(uint4*)(sBh + r * 24 + kh) = pbh;
            *(uint4*)(sBl + r * 24 + kh) = pbl;
        }
        __syncthreads();
        if (kb + 1 < NKB) {
            const float* ap = g_c2m + (size_t)(m0 + r) * FCIN + (kb + 1) * 16 + kh;
            pa0 = *(const float4*)ap; pa1 = *(const float4*)(ap + 4);
            const size_t bo = (size_t)(nb0 + r) * FCIN + (kb + 1) * 16 + kh;
            pbh = *(const uint4*)(g_fwt_hi + bo);
            pbl = *(const uint4*)(g_fwt_lo + bo);
        }

        unsigned ah[2][4], al[2][4];
        #pragma unroll
        for (int mt = 0; mt < 2; mt++) {
            ldsm4(sAh_u + arow[mt], ah[mt][0], ah[mt][1], ah[mt][2], ah[mt][3]);
            ldsm4(sAl_u + arow[mt], al[mt][0], al[mt][1], al[mt][2], al[mt][3]);
        }
        #pragma unroll
        for (int np = 0; np < 2; np++) {
            unsigned bh[4], bl[4];
            ldsm4(sBh_u + bbase + np * 16 * 48, bh[0], bh[1], bh[2], bh[3]);
            ldsm4(sBl_u + bbase + np * 16 * 48, bl[0], bl[1], bl[2], bl[3]);
            #pragma unroll
            for (int mt = 0; mt < 2; mt++) {
                mma16816(acc[mt][np * 2 + 0], ah[mt], bh + 0);
                mma16816(acc[mt][np * 2 + 0], ah[mt], bl + 0);
                mma16816(acc[mt][np * 2 + 0], al[mt], bh + 0);
                mma16816(acc[mt][np * 2 + 1], ah[mt], bh + 2);
                mma16816(acc[mt][np * 2 + 1], ah[mt], bl + 2);
                mma16816(acc[mt][np * 2 + 1], al[mt], bh + 2);
            }
        }
    }

    #pragma unroll
    for (int mt = 0; mt < 2; mt++) {
        const int mrow0 = m0 + wm * 32 + mt * 16 + (lane >> 2);
        #pragma unroll
        for (int hf = 0; hf < 2; hf++) {
            const int m = mrow0 + hf * 8;
            #pragma unroll
            for (int nt = 0; nt < 4; nt++) {
                const int col = nb0 + wn * 32 + nt * 8 + (lane & 3) * 2;
                float2 v;
                v.x = fmaxf(acc[mt][nt][hf * 2 + 0] + __ldg(bias + col), 0.0f);
                v.y = fmaxf(acc[mt][nt][hf * 2 + 1] + __ldg(bias + col + 1), 0.0f);
                *(float2*)(g_fc1 + (size_t)m * FCD + col) = v;
            }
        }
    }
}

// ---------------- FC2 ----------------
__global__ void fc2_kernel(const float* __restrict__ w,
                           const float* __restrict__ b,
                           float* __restrict__ out)
{
    const int warp = (blockIdx.x * blockDim.x + threadIdx.x) >> 5;
    const int lane = threadIdx.x & 31;
    if (warp >= NBOX) return;
    const float* x = g_fc1 + (size_t)warp * FCD;
    float s = 0.0f;
    #pragma unroll
    for (int i = 0; i < 8; i++) s += x[lane + i * 32] * __ldg(w + lane + i * 32);
    #pragma unroll
    for (int o = 16; o; o >>= 1) s += __shfl_xor_sync(0xFFFFFFFFu, s, o);
    if (lane == 0) out[warp] = 1.0f / (1.0f + expf(-(s + b[0])));
}

// ---------------- launch ----------------
extern "C" void kernel_launch(void* const* d_in, const int* in_sizes, int n_in,
                              void* d_out, int out_size)
{
    const float* feat  = (const float*)d_in[0];
    const float* boxes = (const float*)d_in[1];
    const float* w1    = (const float*)d_in[2];
    const float* b1    = (const float*)d_in[3];
    const float* w2    = (const float*)d_in[4];
    const float* b2    = (const float*)d_in[5];
    const float* fw1   = (const float*)d_in[6];
    const float* fb1   = (const float*)d_in[7];
    const float* fw2   = (const float*)d_in[8];
    const float* fb2   = (const float*)d_in[9];
    float* out = (float*)d_out;

    // dynamic smem sizes
    const int SMEM1 = (2 * (2 * 81 * (64 + 8)) + 2 * 128 * 24) * 2;    // 58944
    const int SMEM2 = (2 * (2 * 81 * (128 + 8)) + 2 * 128 * 24) * 2;   // 100416
    cudaFuncSetAttribute(conv_mma<64, true>,   cudaFuncAttributeMaxDynamicSharedMemorySize, SMEM1);
    cudaFuncSetAttribute(conv_mma<128, false>, cudaFuncAttributeMaxDynamicSharedMemorySize, SMEM2);

    const int PREP_TOTAL = PREP_N1 + PREP_N2 + PREP_N3;
    prep_kernel<<<(PREP_TOTAL + 255) / 256, 256>>>(w1, w2, fw1);
    roi_kernel<<<NBOX, 256>>>(feat, boxes);
    conv_mma<64, true>  <<<NBOX / 2, 256, SMEM1>>>(b1);
    conv_mma<128, false><<<NBOX / 2, 256, SMEM2>>>(b2);
    dim3 gfc(NBOX / 64, FCD / 64);
    fc1_mma<<<gfc, 128>>>(fb1);
    fc2_kernel<<<NBOX / 8, 256>>>(fw2, fb2, out);
}